// round 8
// baseline (speedup 1.0000x reference)
#include <cuda_runtime.h>
#include <math.h>

#define NN 50000
#define D  128
#define NE 800000

// ---------------- device scratch (static globals: allowed) ----------------
__device__ float g_norm[NN * D];      // x @ W1            (25.6 MB)
__device__ int   g_deg[NN];
__device__ int   g_off[NN + 1];
__device__ int   g_cur[NN];
__device__ int   g_csr[NE];           // row indices bucketed by destination
__device__ int   g_is64;

// ---------------- K0: zero degree counters + detect edge dtype ------------
__global__ void k_init(const int* __restrict__ ei32) {
    int i = blockIdx.x * blockDim.x + threadIdx.x;
    if (i < NN) g_deg[i] = 0;
    if (blockIdx.x == 0) {
        __shared__ int ok;
        if (threadIdx.x == 0) ok = 1;
        __syncthreads();
        int bad = 0;
        // If data is int64 (LE), words at odd positions are high halves == 0
        // (all values in [0, 50000)). If int32, they are random indices.
        for (int t = threadIdx.x; t < 2048; t += blockDim.x)
            if (ei32[2 * t + 1] != 0) bad = 1;
        if (bad) ok = 0;
        __syncthreads();
        if (threadIdx.x == 0) g_is64 = ok;
    }
}

// ---------------- K1: GEMM  g_norm = x @ W1  (fp32 FFMA) -------------------
// One warp computes 4 full output rows. Lane l owns output columns [4l,4l+4).
// W1 row k (512B) is one LDG.128 per lane per k; W1 (64KB) stays L1-resident.
__global__ void k_gemm(const float* __restrict__ x, const float* __restrict__ W) {
    int gw   = (blockIdx.x * blockDim.x + threadIdx.x) >> 5;
    int lane = threadIdx.x & 31;
    int r0   = gw * 4;
    if (r0 >= NN) return;

    const float* xp = x + (size_t)r0 * D;
    int c = lane * 4;
    float4 a0 = make_float4(0.f, 0.f, 0.f, 0.f);
    float4 a1 = a0, a2 = a0, a3 = a0;

#pragma unroll 8
    for (int k = 0; k < D; k++) {
        float4 w = *(const float4*)(W + k * D + c);
        float x0 = __ldg(xp + k);
        float x1 = __ldg(xp + D + k);
        float x2 = __ldg(xp + 2 * D + k);
        float x3 = __ldg(xp + 3 * D + k);
        a0.x += x0 * w.x; a0.y += x0 * w.y; a0.z += x0 * w.z; a0.w += x0 * w.w;
        a1.x += x1 * w.x; a1.y += x1 * w.y; a1.z += x1 * w.z; a1.w += x1 * w.w;
        a2.x += x2 * w.x; a2.y += x2 * w.y; a2.z += x2 * w.z; a2.w += x2 * w.w;
        a3.x += x3 * w.x; a3.y += x3 * w.y; a3.z += x3 * w.z; a3.w += x3 * w.w;
    }
    float* o = g_norm + (size_t)r0 * D + c;
    *(float4*)(o        ) = a0;
    *(float4*)(o + D    ) = a1;
    *(float4*)(o + 2 * D) = a2;
    *(float4*)(o + 3 * D) = a3;
}

// ---------------- K2: histogram of destination degrees --------------------
__global__ void k_hist(const void* __restrict__ ei) {
    int e = blockIdx.x * blockDim.x + threadIdx.x;   // grid sized exactly NE
    int col;
    if (g_is64) col = (int)((const long long*)ei)[NE + e];
    else        col = ((const int*)ei)[NE + e];
    atomicAdd(&g_deg[col], 1);
}

// ---------------- K3: exclusive prefix scan (single block) ----------------
__global__ void k_scan() {
    __shared__ int s[1024];
    __shared__ int carry;
    int tid = threadIdx.x;
    if (tid == 0) carry = 0;
    __syncthreads();

    for (int base = 0; base < NN; base += 1024) {
        int i = base + tid;
        int v = (i < NN) ? g_deg[i] : 0;
        s[tid] = v;
        __syncthreads();
        // Hillis-Steele inclusive scan
        for (int off = 1; off < 1024; off <<= 1) {
            int t = (tid >= off) ? s[tid - off] : 0;
            __syncthreads();
            s[tid] += t;
            __syncthreads();
        }
        int excl = s[tid] - v + carry;
        if (i < NN) { g_off[i] = excl; g_cur[i] = excl; }
        __syncthreads();              // everyone has read carry & s[1023] path
        if (tid == 0) carry += s[1023];
        __syncthreads();
    }
    if (tid == 0) g_off[NN] = carry;  // == NE
}

// ---------------- K4: bucket placement (build CSR) -------------------------
__global__ void k_place(const void* __restrict__ ei) {
    int e = blockIdx.x * blockDim.x + threadIdx.x;   // grid sized exactly NE
    int row, col;
    if (g_is64) {
        row = (int)((const long long*)ei)[e];
        col = (int)((const long long*)ei)[NE + e];
    } else {
        row = ((const int*)ei)[e];
        col = ((const int*)ei)[NE + e];
    }
    int p = atomicAdd(&g_cur[col], 1);
    g_csr[p] = row;
}

// ---------------- K5: per-destination max-pool + concat --------------------
// One warp per destination node. Lane l owns columns [4l,4l+4). Also copies x
// into out[:, :128] (fused). Empty segments -> zeros (torch_scatter semantics).
__global__ void k_pool(const float* __restrict__ x, float* __restrict__ out) {
    int gw   = (blockIdx.x * blockDim.x + threadIdx.x) >> 5;
    int lane = threadIdx.x & 31;
    if (gw >= NN) return;
    int n = gw, c = lane * 4;

    // concat part 1: copy x row
    float4 xv = *(const float4*)(x + (size_t)n * D + c);
    *(float4*)(out + (size_t)n * (2 * D) + c) = xv;

    int s = g_off[n], e = g_off[n + 1];
    const float NI = __int_as_float(0xff800000);   // -inf
    float4 a0 = make_float4(NI, NI, NI, NI), a1 = a0;

    int i = s;
    for (; i + 2 <= e; i += 2) {                   // 2-way MLP
        int r0 = g_csr[i], r1 = g_csr[i + 1];
        float4 v0 = *(const float4*)(g_norm + (size_t)r0 * D + c);
        float4 v1 = *(const float4*)(g_norm + (size_t)r1 * D + c);
        a0.x = fmaxf(a0.x, v0.x); a0.y = fmaxf(a0.y, v0.y);
        a0.z = fmaxf(a0.z, v0.z); a0.w = fmaxf(a0.w, v0.w);
        a1.x = fmaxf(a1.x, v1.x); a1.y = fmaxf(a1.y, v1.y);
        a1.z = fmaxf(a1.z, v1.z); a1.w = fmaxf(a1.w, v1.w);
    }
    if (i < e) {
        int r0 = g_csr[i];
        float4 v0 = *(const float4*)(g_norm + (size_t)r0 * D + c);
        a0.x = fmaxf(a0.x, v0.x); a0.y = fmaxf(a0.y, v0.y);
        a0.z = fmaxf(a0.z, v0.z); a0.w = fmaxf(a0.w, v0.w);
    }
    float4 r = make_float4(fmaxf(a0.x, a1.x), fmaxf(a0.y, a1.y),
                           fmaxf(a0.z, a1.z), fmaxf(a0.w, a1.w));
    if (s == e) r = make_float4(0.f, 0.f, 0.f, 0.f);
    *(float4*)(out + (size_t)n * (2 * D) + D + c) = r;
}

// ---------------------------------------------------------------------------
extern "C" void kernel_launch(void* const* d_in, const int* in_sizes, int n_in,
                              void* d_out, int out_size) {
    const float* x  = (const float*)d_in[0];
    const float* W  = (const float*)d_in[1];
    const void*  ei = d_in[2];
    float* out = (float*)d_out;

    k_init <<<(NN + 255) / 256, 256>>>((const int*)ei);
    k_gemm <<<(NN / 4 + 7) / 8, 256>>>(x, W);       // 12500 warps, 4 rows each
    k_hist <<<NE / 256, 256>>>(ei);                 // exactly 800000 threads
    k_scan <<<1, 1024>>>();
    k_place<<<NE / 256, 256>>>(ei);
    k_pool <<<NN / 8, 256>>>(x, out);               // exactly 50000 warps
}

// round 9
// speedup vs baseline: 1.0018x; 1.0018x over previous
#include <cuda_runtime.h>
#include <math.h>

#define NN 50000
#define D  128
#define NE 800000

// ---------------- device scratch (static globals: allowed) ----------------
__device__ float g_norm[NN * D];      // x @ W1            (25.6 MB)
__device__ int   g_deg[NN];
__device__ int   g_off[NN + 1];
__device__ int   g_cur[NN];
__device__ int   g_csr[NE];           // row indices bucketed by destination
__device__ int   g_is64;

// ---------------- K0: zero degree counters + detect edge dtype ------------
__global__ void k_init(const int* __restrict__ ei32) {
    int i = blockIdx.x * blockDim.x + threadIdx.x;
    if (i < NN) g_deg[i] = 0;
    if (blockIdx.x == 0) {
        __shared__ int ok;
        if (threadIdx.x == 0) ok = 1;
        __syncthreads();
        int bad = 0;
        // int64 (LE): odd 32-bit words are high halves == 0 (values < 50000).
        // int32: those words are random indices -> nonzero with certainty.
        for (int t = threadIdx.x; t < 2048; t += blockDim.x)
            if (ei32[2 * t + 1] != 0) bad = 1;
        if (bad) ok = 0;
        __syncthreads();
        if (threadIdx.x == 0) g_is64 = ok;
    }
}

// ---------------- K1: GEMM  g_norm = x @ W1  (fp32 FFMA) -------------------
// One warp computes 4 full output rows. Lane l owns output columns [4l,4l+4).
// x broadcasts hoisted to float4 (1 LDG.128 per row per 4 k's).
__global__ void k_gemm(const float* __restrict__ x, const float* __restrict__ W) {
    int gw   = (blockIdx.x * blockDim.x + threadIdx.x) >> 5;
    int lane = threadIdx.x & 31;
    int r0   = gw * 4;
    if (r0 >= NN) return;

    const float* xp = x + (size_t)r0 * D;
    int c = lane * 4;
    float4 a0 = make_float4(0.f, 0.f, 0.f, 0.f);
    float4 a1 = a0, a2 = a0, a3 = a0;

#pragma unroll 2
    for (int k = 0; k < D; k += 4) {
        float4 xv0 = *(const float4*)(xp + k);
        float4 xv1 = *(const float4*)(xp + D + k);
        float4 xv2 = *(const float4*)(xp + 2 * D + k);
        float4 xv3 = *(const float4*)(xp + 3 * D + k);
        const float* px0 = (const float*)&xv0;
        const float* px1 = (const float*)&xv1;
        const float* px2 = (const float*)&xv2;
        const float* px3 = (const float*)&xv3;
#pragma unroll
        for (int kk = 0; kk < 4; kk++) {
            float4 w = *(const float4*)(W + (k + kk) * D + c);
            float x0 = px0[kk], x1 = px1[kk], x2 = px2[kk], x3 = px3[kk];
            a0.x += x0 * w.x; a0.y += x0 * w.y; a0.z += x0 * w.z; a0.w += x0 * w.w;
            a1.x += x1 * w.x; a1.y += x1 * w.y; a1.z += x1 * w.z; a1.w += x1 * w.w;
            a2.x += x2 * w.x; a2.y += x2 * w.y; a2.z += x2 * w.z; a2.w += x2 * w.w;
            a3.x += x3 * w.x; a3.y += x3 * w.y; a3.z += x3 * w.z; a3.w += x3 * w.w;
        }
    }
    float* o = g_norm + (size_t)r0 * D + c;
    *(float4*)(o        ) = a0;
    *(float4*)(o + D    ) = a1;
    *(float4*)(o + 2 * D) = a2;
    *(float4*)(o + 3 * D) = a3;
}

// ---------------- K2: histogram of destination degrees --------------------
__global__ void k_hist(const void* __restrict__ ei) {
    int e = blockIdx.x * blockDim.x + threadIdx.x;   // grid sized exactly NE
    int col;
    if (g_is64) col = (int)((const long long*)ei)[NE + e];
    else        col = ((const int*)ei)[NE + e];
    atomicAdd(&g_deg[col], 1);
}

// ---------------- K3: exclusive prefix scan (single block, shuffle) -------
// Each thread owns 49 contiguous elements (1024*49 = 50176 >= NN).
// Pass 1: private sum (no sync). Block scan of 1024 partials via warp
// shuffles (2 __syncthreads total). Pass 2: serial exclusive write-out.
__global__ void k_scan() {
    const int PER = 49;
    int tid  = threadIdx.x;
    int lane = tid & 31, wid = tid >> 5;
    int base = tid * PER;

    int sum = 0;
    for (int j = 0; j < PER; j++) {
        int i = base + j;
        if (i < NN) sum += g_deg[i];
    }

    // inclusive warp scan of per-thread sums
    int v = sum;
#pragma unroll
    for (int off = 1; off < 32; off <<= 1) {
        int t = __shfl_up_sync(0xffffffffu, v, off);
        if (lane >= off) v += t;
    }
    __shared__ int wsum[32];
    if (lane == 31) wsum[wid] = v;
    __syncthreads();
    if (wid == 0) {
        int w = wsum[lane];
#pragma unroll
        for (int off = 1; off < 32; off <<= 1) {
            int t = __shfl_up_sync(0xffffffffu, w, off);
            if (lane >= off) w += t;
        }
        wsum[lane] = w;
    }
    __syncthreads();

    int excl = v - sum + (wid > 0 ? wsum[wid - 1] : 0);

    int run = excl;
    for (int j = 0; j < PER; j++) {
        int i = base + j;
        if (i < NN) {
            g_off[i] = run;
            g_cur[i] = run;
            run += g_deg[i];
        }
    }
    if (tid == 1023) g_off[NN] = excl;   // tid 1023 covers i >= NN only
}

// ---------------- K4: bucket placement (build CSR) -------------------------
__global__ void k_place(const void* __restrict__ ei) {
    int e = blockIdx.x * blockDim.x + threadIdx.x;   // grid sized exactly NE
    int row, col;
    if (g_is64) {
        row = (int)((const long long*)ei)[e];
        col = (int)((const long long*)ei)[NE + e];
    } else {
        row = ((const int*)ei)[e];
        col = ((const int*)ei)[NE + e];
    }
    int p = atomicAdd(&g_cur[col], 1);
    g_csr[p] = row;
}

// ---------------- K5: per-destination max-pool + concat --------------------
// One warp per destination node. Lane l owns columns [4l,4l+4). Also copies x
// into out[:, :128] (fused). Empty segments -> zeros (torch_scatter semantics).
__global__ void k_pool(const float* __restrict__ x, float* __restrict__ out) {
    int gw   = (blockIdx.x * blockDim.x + threadIdx.x) >> 5;
    int lane = threadIdx.x & 31;
    if (gw >= NN) return;
    int n = gw, c = lane * 4;

    // concat part 1: copy x row
    float4 xv = *(const float4*)(x + (size_t)n * D + c);
    *(float4*)(out + (size_t)n * (2 * D) + c) = xv;

    int s = g_off[n], e = g_off[n + 1];
    const float NI = __int_as_float(0xff800000);   // -inf
    float4 a0 = make_float4(NI, NI, NI, NI), a1 = a0;

    int i = s;
    for (; i + 2 <= e; i += 2) {                   // 2-way MLP
        int r0 = g_csr[i], r1 = g_csr[i + 1];
        float4 v0 = *(const float4*)(g_norm + (size_t)r0 * D + c);
        float4 v1 = *(const float4*)(g_norm + (size_t)r1 * D + c);
        a0.x = fmaxf(a0.x, v0.x); a0.y = fmaxf(a0.y, v0.y);
        a0.z = fmaxf(a0.z, v0.z); a0.w = fmaxf(a0.w, v0.w);
        a1.x = fmaxf(a1.x, v1.x); a1.y = fmaxf(a1.y, v1.y);
        a1.z = fmaxf(a1.z, v1.z); a1.w = fmaxf(a1.w, v1.w);
    }
    if (i < e) {
        int r0 = g_csr[i];
        float4 v0 = *(const float4*)(g_norm + (size_t)r0 * D + c);
        a0.x = fmaxf(a0.x, v0.x); a0.y = fmaxf(a0.y, v0.y);
        a0.z = fmaxf(a0.z, v0.z); a0.w = fmaxf(a0.w, v0.w);
    }
    float4 r = make_float4(fmaxf(a0.x, a1.x), fmaxf(a0.y, a1.y),
                           fmaxf(a0.z, a1.z), fmaxf(a0.w, a1.w));
    if (s == e) r = make_float4(0.f, 0.f, 0.f, 0.f);
    *(float4*)(out + (size_t)n * (2 * D) + D + c) = r;
}

// ---------------------------------------------------------------------------
extern "C" void kernel_launch(void* const* d_in, const int* in_sizes, int n_in,
                              void* d_out, int out_size) {
    const float* x  = (const float*)d_in[0];
    const float* W  = (const float*)d_in[1];
    const void*  ei = d_in[2];
    float* out = (float*)d_out;

    k_init <<<(NN + 255) / 256, 256>>>((const int*)ei);
    k_gemm <<<(NN / 4 + 7) / 8, 256>>>(x, W);       // 12500 warps, 4 rows each
    k_hist <<<NE / 256, 256>>>(ei);                 // exactly 800000 threads
    k_scan <<<1, 1024>>>();
    k_place<<<NE / 256, 256>>>(ei);
    k_pool <<<NN / 8, 256>>>(x, out);               // exactly 50000 warps
}

// round 10
// speedup vs baseline: 1.4330x; 1.4304x over previous
#include <cuda_runtime.h>
#include <math.h>

#define NN 50000
#define D  128
#define NE 800000

// ---------------- device scratch (static globals: allowed) ----------------
__device__ __align__(16) float g_norm[NN * D];   // x @ W1 (25.6 MB)
__device__ __align__(16) int   g_deg[NN];
__device__ __align__(16) int   g_off[NN + 4];    // padded for int4 stores
__device__ __align__(16) int   g_cur[NN];
__device__ int   g_csr[NE];                      // rows bucketed by dest
__device__ int   g_is64;

// ---------------- K0: zero degree counters + detect edge dtype ------------
__global__ void k_init(const int* __restrict__ ei32) {
    int i = blockIdx.x * blockDim.x + threadIdx.x;
    if (i < NN) g_deg[i] = 0;
    if (blockIdx.x == 0) {
        __shared__ int ok;
        if (threadIdx.x == 0) ok = 1;
        __syncthreads();
        int bad = 0;
        // int64 (LE): odd 32-bit words are high halves == 0 (values < 50000).
        // int32: those words are random indices -> nonzero with certainty.
        for (int t = threadIdx.x; t < 2048; t += blockDim.x)
            if (ei32[2 * t + 1] != 0) bad = 1;
        if (bad) ok = 0;
        __syncthreads();
        if (threadIdx.x == 0) g_is64 = ok;
    }
}

// ---------------- K1: GEMM  g_norm = x @ W1  (fp32 FFMA) -------------------
// One warp computes 4 full output rows. Lane l owns output columns [4l,4l+4).
__global__ void k_gemm(const float* __restrict__ x, const float* __restrict__ W) {
    int gw   = (blockIdx.x * blockDim.x + threadIdx.x) >> 5;
    int lane = threadIdx.x & 31;
    int r0   = gw * 4;
    if (r0 >= NN) return;

    const float* xp = x + (size_t)r0 * D;
    int c = lane * 4;
    float4 a0 = make_float4(0.f, 0.f, 0.f, 0.f);
    float4 a1 = a0, a2 = a0, a3 = a0;

#pragma unroll 2
    for (int k = 0; k < D; k += 4) {
        float4 xv0 = *(const float4*)(xp + k);
        float4 xv1 = *(const float4*)(xp + D + k);
        float4 xv2 = *(const float4*)(xp + 2 * D + k);
        float4 xv3 = *(const float4*)(xp + 3 * D + k);
        const float* px0 = (const float*)&xv0;
        const float* px1 = (const float*)&xv1;
        const float* px2 = (const float*)&xv2;
        const float* px3 = (const float*)&xv3;
#pragma unroll
        for (int kk = 0; kk < 4; kk++) {
            float4 w = *(const float4*)(W + (k + kk) * D + c);
            float x0 = px0[kk], x1 = px1[kk], x2 = px2[kk], x3 = px3[kk];
            a0.x += x0 * w.x; a0.y += x0 * w.y; a0.z += x0 * w.z; a0.w += x0 * w.w;
            a1.x += x1 * w.x; a1.y += x1 * w.y; a1.z += x1 * w.z; a1.w += x1 * w.w;
            a2.x += x2 * w.x; a2.y += x2 * w.y; a2.z += x2 * w.z; a2.w += x2 * w.w;
            a3.x += x3 * w.x; a3.y += x3 * w.y; a3.z += x3 * w.z; a3.w += x3 * w.w;
        }
    }
    float* o = g_norm + (size_t)r0 * D + c;
    *(float4*)(o        ) = a0;
    *(float4*)(o + D    ) = a1;
    *(float4*)(o + 2 * D) = a2;
    *(float4*)(o + 3 * D) = a3;
}

// ---------------- K2: histogram of destination degrees --------------------
__global__ void k_hist(const void* __restrict__ ei) {
    int e = blockIdx.x * blockDim.x + threadIdx.x;   // grid sized exactly NE
    int col;
    if (g_is64) col = (int)((const long long*)ei)[NE + e];
    else        col = ((const int*)ei)[NE + e];
    atomicAdd(&g_deg[col], 1);
}

// ---------------- K3: exclusive scan — tiled, COALESCED --------------------
// 13 tiles of 4096. Per tile: one coalesced int4 load per thread (lanes
// adjacent -> 1 line per 4 lanes), in-register 4-scan, warp-shuffle scan,
// 32-warp combine in smem, coalesced int4 stores, single smem carry.
__global__ void k_scan() {
    __shared__ int wsum[32];
    __shared__ int s_carry;
    int tid = threadIdx.x, lane = tid & 31, wid = tid >> 5;
    if (tid == 0) s_carry = 0;
    __syncthreads();

    const int NT4 = NN / 4;                      // 12500 int4 groups
    for (int base = 0; base < NT4; base += 1024) {
        int g = base + tid;
        int4 d = make_int4(0, 0, 0, 0);
        if (g < NT4) d = ((const int4*)g_deg)[g];
        int s0 = d.x;
        int s1 = s0 + d.y;
        int s2 = s1 + d.z;
        int s3 = s2 + d.w;                       // thread-inclusive total

        int v = s3;                              // warp inclusive scan
#pragma unroll
        for (int off = 1; off < 32; off <<= 1) {
            int t = __shfl_up_sync(0xffffffffu, v, off);
            if (lane >= off) v += t;
        }
        if (lane == 31) wsum[wid] = v;
        __syncthreads();
        if (wid == 0) {
            int w = wsum[lane];
#pragma unroll
            for (int off = 1; off < 32; off <<= 1) {
                int t = __shfl_up_sync(0xffffffffu, w, off);
                if (lane >= off) w += t;
            }
            wsum[lane] = w;
        }
        __syncthreads();

        int carry = s_carry;
        int excl = v - s3 + (wid ? wsum[wid - 1] : 0) + carry;
        if (g < NT4) {
            int4 o = make_int4(excl, excl + s0, excl + s1, excl + s2);
            ((int4*)g_off)[g] = o;
            ((int4*)g_cur)[g] = o;
        }
        __syncthreads();                         // all have read carry/wsum
        if (tid == 0) s_carry = carry + wsum[31];
        __syncthreads();                         // carry visible for next tile
    }
    if (tid == 0) g_off[NN] = s_carry;           // == NE
}

// ---------------- K4: bucket placement (build CSR) -------------------------
__global__ void k_place(const void* __restrict__ ei) {
    int e = blockIdx.x * blockDim.x + threadIdx.x;   // grid sized exactly NE
    int row, col;
    if (g_is64) {
        row = (int)((const long long*)ei)[e];
        col = (int)((const long long*)ei)[NE + e];
    } else {
        row = ((const int*)ei)[e];
        col = ((const int*)ei)[NE + e];
    }
    int p = atomicAdd(&g_cur[col], 1);
    g_csr[p] = row;
}

// ---------------- K5: per-destination max-pool + concat --------------------
// One warp per destination node. Lane l owns columns [4l,4l+4). Also copies x
// into out[:, :128] (fused). Empty segments -> zeros (torch_scatter semantics).
__global__ void k_pool(const float* __restrict__ x, float* __restrict__ out) {
    int gw   = (blockIdx.x * blockDim.x + threadIdx.x) >> 5;
    int lane = threadIdx.x & 31;
    if (gw >= NN) return;
    int n = gw, c = lane * 4;

    // concat part 1: copy x row
    float4 xv = *(const float4*)(x + (size_t)n * D + c);
    *(float4*)(out + (size_t)n * (2 * D) + c) = xv;

    int s = g_off[n], e = g_off[n + 1];
    const float NI = __int_as_float(0xff800000);   // -inf
    float4 a0 = make_float4(NI, NI, NI, NI), a1 = a0;

    int i = s;
    for (; i + 2 <= e; i += 2) {                   // 2-way MLP
        int r0 = g_csr[i], r1 = g_csr[i + 1];
        float4 v0 = *(const float4*)(g_norm + (size_t)r0 * D + c);
        float4 v1 = *(const float4*)(g_norm + (size_t)r1 * D + c);
        a0.x = fmaxf(a0.x, v0.x); a0.y = fmaxf(a0.y, v0.y);
        a0.z = fmaxf(a0.z, v0.z); a0.w = fmaxf(a0.w, v0.w);
        a1.x = fmaxf(a1.x, v1.x); a1.y = fmaxf(a1.y, v1.y);
        a1.z = fmaxf(a1.z, v1.z); a1.w = fmaxf(a1.w, v1.w);
    }
    if (i < e) {
        int r0 = g_csr[i];
        float4 v0 = *(const float4*)(g_norm + (size_t)r0 * D + c);
        a0.x = fmaxf(a0.x, v0.x); a0.y = fmaxf(a0.y, v0.y);
        a0.z = fmaxf(a0.z, v0.z); a0.w = fmaxf(a0.w, v0.w);
    }
    float4 r = make_float4(fmaxf(a0.x, a1.x), fmaxf(a0.y, a1.y),
                           fmaxf(a0.z, a1.z), fmaxf(a0.w, a1.w));
    if (s == e) r = make_float4(0.f, 0.f, 0.f, 0.f);
    *(float4*)(out + (size_t)n * (2 * D) + D + c) = r;
}

// ---------------------------------------------------------------------------
extern "C" void kernel_launch(void* const* d_in, const int* in_sizes, int n_in,
                              void* d_out, int out_size) {
    const float* x  = (const float*)d_in[0];
    const float* W  = (const float*)d_in[1];
    const void*  ei = d_in[2];
    float* out = (float*)d_out;

    k_init <<<(NN + 255) / 256, 256>>>((const int*)ei);
    k_gemm <<<(NN / 4 + 7) / 8, 256>>>(x, W);       // 12500 warps, 4 rows each
    k_hist <<<NE / 256, 256>>>(ei);                 // exactly 800000 threads
    k_scan <<<1, 1024>>>();
    k_place<<<NE / 256, 256>>>(ei);
    k_pool <<<NN / 8, 256>>>(x, out);               // exactly 50000 warps
}

// round 11
// speedup vs baseline: 1.5939x; 1.1123x over previous
#include <cuda_runtime.h>
#include <math.h>

#define NN 50000
#define D  128
#define NE 800000

// ---------------- device scratch (static globals: allowed) ----------------
__device__ __align__(16) float g_norm[NN * D];   // x @ W1 (25.6 MB)
__device__ __align__(16) int   g_deg[NN];
__device__ __align__(16) int   g_off[NN + 4];    // padded for int4 stores
__device__ __align__(16) int   g_cur[NN];
__device__ int   g_csr[NE];                      // rows bucketed by dest
__device__ int   g_is64;

// ---- f32x2 packed-FMA helpers (sm_103a FFMA2 path, PTX-only) --------------
__device__ __forceinline__ unsigned long long splat2(float x) {
    unsigned long long r;
    asm("mov.b64 %0, {%1, %1};" : "=l"(r) : "f"(x));
    return r;
}
__device__ __forceinline__ void ffma2(unsigned long long& acc,
                                      unsigned long long a,
                                      unsigned long long b) {
    asm("fma.rn.f32x2 %0, %1, %2, %0;" : "+l"(acc) : "l"(a), "l"(b));
}
__device__ __forceinline__ float2 unpack2(unsigned long long v) {
    float lo, hi;
    asm("mov.b64 {%0, %1}, %2;" : "=f"(lo), "=f"(hi) : "l"(v));
    return make_float2(lo, hi);
}

// ---------------- K0: zero degree counters + detect edge dtype ------------
__global__ void k_init(const int* __restrict__ ei32) {
    int i = blockIdx.x * blockDim.x + threadIdx.x;
    if (i < NN) g_deg[i] = 0;
    if (blockIdx.x == 0) {
        __shared__ int ok;
        if (threadIdx.x == 0) ok = 1;
        __syncthreads();
        int bad = 0;
        // int64 (LE): odd 32-bit words are high halves == 0 (values < 50000).
        // int32: those words are random indices -> nonzero with certainty.
        for (int t = threadIdx.x; t < 2048; t += blockDim.x)
            if (ei32[2 * t + 1] != 0) bad = 1;
        if (bad) ok = 0;
        __syncthreads();
        if (threadIdx.x == 0) g_is64 = ok;
    }
}

// ---------------- K1: GEMM  g_norm = x @ W1  (packed f32x2 FMA) ------------
// One warp computes 4 output rows. Lane l owns cols [4l,4l+4) as 2 f32x2.
// FMA-pipe work halved vs scalar FFMA; x-splats ride the alu pipe.
__global__ void k_gemm(const float* __restrict__ x, const float* __restrict__ W) {
    int gw   = (blockIdx.x * blockDim.x + threadIdx.x) >> 5;
    int lane = threadIdx.x & 31;
    int r0   = gw * 4;
    if (r0 >= NN) return;

    const float* xp = x + (size_t)r0 * D;
    int c = lane * 4;

    unsigned long long acc[4][2];
#pragma unroll
    for (int r = 0; r < 4; r++) { acc[r][0] = 0ull; acc[r][1] = 0ull; }

#pragma unroll 2
    for (int k = 0; k < D; k += 4) {
        float4 xv0 = *(const float4*)(xp + k);
        float4 xv1 = *(const float4*)(xp + D + k);
        float4 xv2 = *(const float4*)(xp + 2 * D + k);
        float4 xv3 = *(const float4*)(xp + 3 * D + k);
        const float* px0 = (const float*)&xv0;
        const float* px1 = (const float*)&xv1;
        const float* px2 = (const float*)&xv2;
        const float* px3 = (const float*)&xv3;
#pragma unroll
        for (int kk = 0; kk < 4; kk++) {
            ulonglong2 w = *(const ulonglong2*)(W + (k + kk) * D + c);
            unsigned long long b0 = splat2(px0[kk]);
            unsigned long long b1 = splat2(px1[kk]);
            unsigned long long b2 = splat2(px2[kk]);
            unsigned long long b3 = splat2(px3[kk]);
            ffma2(acc[0][0], w.x, b0); ffma2(acc[0][1], w.y, b0);
            ffma2(acc[1][0], w.x, b1); ffma2(acc[1][1], w.y, b1);
            ffma2(acc[2][0], w.x, b2); ffma2(acc[2][1], w.y, b2);
            ffma2(acc[3][0], w.x, b3); ffma2(acc[3][1], w.y, b3);
        }
    }

    float* o = g_norm + (size_t)r0 * D + c;
#pragma unroll
    for (int r = 0; r < 4; r++) {
        float2 lo = unpack2(acc[r][0]);
        float2 hi = unpack2(acc[r][1]);
        *(float4*)(o + (size_t)r * D) = make_float4(lo.x, lo.y, hi.x, hi.y);
    }
}

// ---------------- K2: histogram of destination degrees --------------------
__global__ void k_hist(const void* __restrict__ ei) {
    int e = blockIdx.x * blockDim.x + threadIdx.x;   // grid sized exactly NE
    int col;
    if (g_is64) col = (int)((const long long*)ei)[NE + e];
    else        col = ((const int*)ei)[NE + e];
    atomicAdd(&g_deg[col], 1);
}

// ---------------- K3: exclusive scan — warp-owned hierarchical ------------
// 32 warps, each owns a contiguous slice of ~391 int4 groups (lane-adjacent
// within an iteration -> coalesced). Only 2 block barriers total; phase-2
// carry chain is pure warp shuffles, reloads hit L1 (g_deg = 200KB).
__global__ void k_scan() {
    __shared__ int wtot[33];
    int tid = threadIdx.x, lane = tid & 31, wid = tid >> 5;
    const int NT4  = NN / 4;                       // 12500 int4 groups
    const int PERW = (NT4 + 31) / 32;              // 391
    int g0 = wid * PERW;
    int g1 = min(g0 + PERW, NT4);

    // Phase 1: warp totals (independent coalesced loads, MLP overlap)
    int sum = 0;
    for (int g = g0 + lane; g < g1; g += 32) {
        int4 d = ((const int4*)g_deg)[g];
        sum += d.x + d.y + d.z + d.w;
    }
#pragma unroll
    for (int off = 16; off > 0; off >>= 1)
        sum += __shfl_xor_sync(0xffffffffu, sum, off);
    if (lane == 0) wtot[wid] = sum;
    __syncthreads();

    // Block scan of 32 warp totals (warp 0)
    if (wid == 0) {
        int w = wtot[lane];
#pragma unroll
        for (int off = 1; off < 32; off <<= 1) {
            int t = __shfl_up_sync(0xffffffffu, w, off);
            if (lane >= off) w += t;
        }
        wtot[lane] = w;                            // inclusive
    }
    __syncthreads();

    // Phase 2: per-warp serial walk, intra-warp shuffle carry
    int carry = wid ? wtot[wid - 1] : 0;
    for (int gb = g0; gb < g1; gb += 32) {
        int g = gb + lane;
        int4 d = make_int4(0, 0, 0, 0);
        if (g < g1) d = ((const int4*)g_deg)[g];
        int s0 = d.x, s1 = s0 + d.y, s2 = s1 + d.z, s3 = s2 + d.w;

        int v = s3;
#pragma unroll
        for (int off = 1; off < 32; off <<= 1) {
            int t = __shfl_up_sync(0xffffffffu, v, off);
            if (lane >= off) v += t;
        }
        int excl = carry + v - s3;
        if (g < g1) {
            int4 o = make_int4(excl, excl + s0, excl + s1, excl + s2);
            ((int4*)g_off)[g] = o;
            ((int4*)g_cur)[g] = o;
        }
        carry += __shfl_sync(0xffffffffu, v, 31);
    }
    if (wid == 31 && lane == 0) g_off[NN] = carry; // == NE
}

// ---------------- K4: bucket placement (build CSR) -------------------------
__global__ void k_place(const void* __restrict__ ei) {
    int e = blockIdx.x * blockDim.x + threadIdx.x;   // grid sized exactly NE
    int row, col;
    if (g_is64) {
        row = (int)((const long long*)ei)[e];
        col = (int)((const long long*)ei)[NE + e];
    } else {
        row = ((const int*)ei)[e];
        col = ((const int*)ei)[NE + e];
    }
    int p = atomicAdd(&g_cur[col], 1);
    g_csr[p] = row;
}

// ---------------- K5: per-destination max-pool + concat --------------------
// One warp per destination node. Lane l owns columns [4l,4l+4). Also copies x
// into out[:, :128] (fused). Empty segments -> zeros (torch_scatter semantics).
__global__ void k_pool(const float* __restrict__ x, float* __restrict__ out) {
    int gw   = (blockIdx.x * blockDim.x + threadIdx.x) >> 5;
    int lane = threadIdx.x & 31;
    if (gw >= NN) return;
    int n = gw, c = lane * 4;

    // concat part 1: copy x row
    float4 xv = *(const float4*)(x + (size_t)n * D + c);
    *(float4*)(out + (size_t)n * (2 * D) + c) = xv;

    int s = g_off[n], e = g_off[n + 1];
    const float NI = __int_as_float(0xff800000);   // -inf
    float4 a0 = make_float4(NI, NI, NI, NI), a1 = a0;

    int i = s;
    for (; i + 2 <= e; i += 2) {                   // 2-way MLP
        int r0 = g_csr[i], r1 = g_csr[i + 1];
        float4 v0 = *(const float4*)(g_norm + (size_t)r0 * D + c);
        float4 v1 = *(const float4*)(g_norm + (size_t)r1 * D + c);
        a0.x = fmaxf(a0.x, v0.x); a0.y = fmaxf(a0.y, v0.y);
        a0.z = fmaxf(a0.z, v0.z); a0.w = fmaxf(a0.w, v0.w);
        a1.x = fmaxf(a1.x, v1.x); a1.y = fmaxf(a1.y, v1.y);
        a1.z = fmaxf(a1.z, v1.z); a1.w = fmaxf(a1.w, v1.w);
    }
    if (i < e) {
        int r0 = g_csr[i];
        float4 v0 = *(const float4*)(g_norm + (size_t)r0 * D + c);
        a0.x = fmaxf(a0.x, v0.x); a0.y = fmaxf(a0.y, v0.y);
        a0.z = fmaxf(a0.z, v0.z); a0.w = fmaxf(a0.w, v0.w);
    }
    float4 r = make_float4(fmaxf(a0.x, a1.x), fmaxf(a0.y, a1.y),
                           fmaxf(a0.z, a1.z), fmaxf(a0.w, a1.w));
    if (s == e) r = make_float4(0.f, 0.f, 0.f, 0.f);
    *(float4*)(out + (size_t)n * (2 * D) + D + c) = r;
}

// ---------------------------------------------------------------------------
extern "C" void kernel_launch(void* const* d_in, const int* in_sizes, int n_in,
                              void* d_out, int out_size) {
    const float* x  = (const float*)d_in[0];
    const float* W  = (const float*)d_in[1];
    const void*  ei = d_in[2];
    float* out = (float*)d_out;

    k_init <<<(NN + 255) / 256, 256>>>((const int*)ei);
    k_gemm <<<(NN / 4 + 7) / 8, 256>>>(x, W);       // 12500 warps, 4 rows each
    k_hist <<<NE / 256, 256>>>(ei);                 // exactly 800000 threads
    k_scan <<<1, 1024>>>();
    k_place<<<NE / 256, 256>>>(ei);
    k_pool <<<NN / 8, 256>>>(x, out);               // exactly 50000 warps
}

// round 13
// speedup vs baseline: 1.7742x; 1.1132x over previous
#include <cuda_runtime.h>
#include <math.h>

#define NN 50000
#define D  128
#define NE 800000

// ---------------- device scratch (static globals: allowed) ----------------
__device__ __align__(16) float g_norm[NN * D];   // x @ W1 (25.6 MB)
__device__ __align__(16) int   g_deg[NN];
__device__ __align__(16) int   g_off[NN + 4];    // padded for int4 stores
__device__ __align__(16) int   g_cur[NN];
__device__ int   g_csr[NE];                      // rows bucketed by dest
__device__ int   g_is64;

// ---- f32x2 packed-FMA helpers (sm_103a FFMA2 path, PTX-only) --------------
__device__ __forceinline__ unsigned long long splat2(float x) {
    unsigned long long r;
    asm("mov.b64 %0, {%1, %1};" : "=l"(r) : "f"(x));
    return r;
}
__device__ __forceinline__ void ffma2(unsigned long long& acc,
                                      unsigned long long a,
                                      unsigned long long b) {
    asm("fma.rn.f32x2 %0, %1, %2, %0;" : "+l"(acc) : "l"(a), "l"(b));
}
__device__ __forceinline__ float2 unpack2(unsigned long long v) {
    float lo, hi;
    asm("mov.b64 {%0, %1}, %2;" : "=f"(lo), "=f"(hi) : "l"(v));
    return make_float2(lo, hi);
}

// ---------------- K0: zero degree counters + detect edge dtype ------------
__global__ void k_init(const int* __restrict__ ei32) {
    int i = blockIdx.x * blockDim.x + threadIdx.x;
    if (i < NN) g_deg[i] = 0;
    if (blockIdx.x == 0) {
        __shared__ int ok;
        if (threadIdx.x == 0) ok = 1;
        __syncthreads();
        int bad = 0;
        // int64 (LE): odd 32-bit words are high halves == 0 (values < 50000).
        // int32: those words are random indices -> nonzero with certainty.
        for (int t = threadIdx.x; t < 2048; t += blockDim.x)
            if (ei32[2 * t + 1] != 0) bad = 1;
        if (bad) ok = 0;
        __syncthreads();
        if (threadIdx.x == 0) g_is64 = ok;
    }
}

// ---------------- K1: GEMM  g_norm = x @ W1  (packed f32x2 FMA) ------------
__global__ void k_gemm(const float* __restrict__ x, const float* __restrict__ W) {
    int gw   = (blockIdx.x * blockDim.x + threadIdx.x) >> 5;
    int lane = threadIdx.x & 31;
    int r0   = gw * 4;
    if (r0 >= NN) return;

    const float* xp = x + (size_t)r0 * D;
    int c = lane * 4;

    unsigned long long acc[4][2];
#pragma unroll
    for (int r = 0; r < 4; r++) { acc[r][0] = 0ull; acc[r][1] = 0ull; }

#pragma unroll 2
    for (int k = 0; k < D; k += 4) {
        float4 xv0 = *(const float4*)(xp + k);
        float4 xv1 = *(const float4*)(xp + D + k);
        float4 xv2 = *(const float4*)(xp + 2 * D + k);
        float4 xv3 = *(const float4*)(xp + 3 * D + k);
        const float* px0 = (const float*)&xv0;
        const float* px1 = (const float*)&xv1;
        const float* px2 = (const float*)&xv2;
        const float* px3 = (const float*)&xv3;
#pragma unroll
        for (int kk = 0; kk < 4; kk++) {
            ulonglong2 w = *(const ulonglong2*)(W + (k + kk) * D + c);
            unsigned long long b0 = splat2(px0[kk]);
            unsigned long long b1 = splat2(px1[kk]);
            unsigned long long b2 = splat2(px2[kk]);
            unsigned long long b3 = splat2(px3[kk]);
            ffma2(acc[0][0], w.x, b0); ffma2(acc[0][1], w.y, b0);
            ffma2(acc[1][0], w.x, b1); ffma2(acc[1][1], w.y, b1);
            ffma2(acc[2][0], w.x, b2); ffma2(acc[2][1], w.y, b2);
            ffma2(acc[3][0], w.x, b3); ffma2(acc[3][1], w.y, b3);
        }
    }

    float* o = g_norm + (size_t)r0 * D + c;
#pragma unroll
    for (int r = 0; r < 4; r++) {
        float2 lo = unpack2(acc[r][0]);
        float2 hi = unpack2(acc[r][1]);
        *(float4*)(o + (size_t)r * D) = make_float4(lo.x, lo.y, hi.x, hi.y);
    }
}

// ---------------- K2: histogram of destination degrees --------------------
__global__ void k_hist(const void* __restrict__ ei) {
    int e = blockIdx.x * blockDim.x + threadIdx.x;   // grid sized exactly NE
    int col;
    if (g_is64) col = (int)((const long long*)ei)[NE + e];
    else        col = ((const int*)ei)[NE + e];
    atomicAdd(&g_deg[col], 1);
}

// ---------------- K3: exclusive scan — batched ILP, reg-bounded ------------
// Phase 1: streaming warp totals (register-light). Phase 2: 13 iterations in
// batches of 5 — loads + warp scans independent within a batch (L1 hits),
// only the carry combine is serial. __launch_bounds__(1024) => <=64 regs.
__global__ void __launch_bounds__(1024) k_scan() {
    __shared__ int wtot[32];
    int tid = threadIdx.x, lane = tid & 31, wid = tid >> 5;
    const int NT4 = NN / 4;                        // 12500 int4 groups
    const int PERW = 391, ITER = 13, B = 5;
    int g0 = wid * PERW;
    int g1 = min(g0 + PERW, NT4);

    // Phase 1: warp totals
    int sum = 0;
    for (int g = g0 + lane; g < g1; g += 32) {
        int4 d = ((const int4*)g_deg)[g];
        sum += d.x + d.y + d.z + d.w;
    }
#pragma unroll
    for (int off = 16; off > 0; off >>= 1)
        sum += __shfl_xor_sync(0xffffffffu, sum, off);
    if (lane == 0) wtot[wid] = sum;
    __syncthreads();
    if (wid == 0) {
        int w = wtot[lane];
#pragma unroll
        for (int off = 1; off < 32; off <<= 1) {
            int t = __shfl_up_sync(0xffffffffu, w, off);
            if (lane >= off) w += t;
        }
        wtot[lane] = w;                            // inclusive
    }
    __syncthreads();

    // Phase 2: batched write-out
    int carry = wid ? wtot[wid - 1] : 0;
#pragma unroll
    for (int b = 0; b < ITER; b += B) {
        int4 d[B]; int s3v[B], inc[B];
#pragma unroll
        for (int j = 0; j < B; j++) {
            int i = b + j;
            int g = g0 + i * 32 + lane;
            d[j] = (i < ITER && g < g1) ? ((const int4*)g_deg)[g]
                                        : make_int4(0, 0, 0, 0);
        }
#pragma unroll
        for (int j = 0; j < B; j++) {
            s3v[j] = d[j].x + d[j].y + d[j].z + d[j].w;
            int v = s3v[j];
#pragma unroll
            for (int off = 1; off < 32; off <<= 1) {
                int t = __shfl_up_sync(0xffffffffu, v, off);
                if (lane >= off) v += t;
            }
            inc[j] = v;
        }
#pragma unroll
        for (int j = 0; j < B; j++) {
            int i = b + j;
            int g = g0 + i * 32 + lane;
            if (i < ITER && g < g1) {
                int excl = carry + inc[j] - s3v[j];
                int t0 = d[j].x, t1 = t0 + d[j].y, t2 = t1 + d[j].z;
                int4 o = make_int4(excl, excl + t0, excl + t1, excl + t2);
                ((int4*)g_off)[g] = o;
                ((int4*)g_cur)[g] = o;
            }
            carry += __shfl_sync(0xffffffffu, inc[j], 31);
        }
    }
    if (tid == 0) g_off[NN] = wtot[31];            // == NE (NN % 4 == 0)
}

// ---------------- K4: bucket placement (build CSR) -------------------------
__global__ void k_place(const void* __restrict__ ei) {
    int e = blockIdx.x * blockDim.x + threadIdx.x;   // grid sized exactly NE
    int row, col;
    if (g_is64) {
        row = (int)((const long long*)ei)[e];
        col = (int)((const long long*)ei)[NE + e];
    } else {
        row = ((const int*)ei)[e];
        col = ((const int*)ei)[NE + e];
    }
    int p = atomicAdd(&g_cur[col], 1);
    g_csr[p] = row;
}

// ---------------- K5: per-destination max-pool + concat --------------------
__global__ void k_pool(const float* __restrict__ x, float* __restrict__ out) {
    int gw   = (blockIdx.x * blockDim.x + threadIdx.x) >> 5;
    int lane = threadIdx.x & 31;
    if (gw >= NN) return;
    int n = gw, c = lane * 4;

    // concat part 1: copy x row
    float4 xv = *(const float4*)(x + (size_t)n * D + c);
    *(float4*)(out + (size_t)n * (2 * D) + c) = xv;

    int s = g_off[n], e = g_off[n + 1];
    const float NI = __int_as_float(0xff800000);   // -inf
    float4 a0 = make_float4(NI, NI, NI, NI), a1 = a0;

    int i = s;
    for (; i + 2 <= e; i += 2) {                   // 2-way MLP
        int r0 = g_csr[i], r1 = g_csr[i + 1];
        float4 v0 = *(const float4*)(g_norm + (size_t)r0 * D + c);
        float4 v1 = *(const float4*)(g_norm + (size_t)r1 * D + c);
        a0.x = fmaxf(a0.x, v0.x); a0.y = fmaxf(a0.y, v0.y);
        a0.z = fmaxf(a0.z, v0.z); a0.w = fmaxf(a0.w, v0.w);
        a1.x = fmaxf(a1.x, v1.x); a1.y = fmaxf(a1.y, v1.y);
        a1.z = fmaxf(a1.z, v1.z); a1.w = fmaxf(a1.w, v1.w);
    }
    if (i < e) {
        int r0 = g_csr[i];
        float4 v0 = *(const float4*)(g_norm + (size_t)r0 * D + c);
        a0.x = fmaxf(a0.x, v0.x); a0.y = fmaxf(a0.y, v0.y);
        a0.z = fmaxf(a0.z, v0.z); a0.w = fmaxf(a0.w, v0.w);
    }
    float4 r = make_float4(fmaxf(a0.x, a1.x), fmaxf(a0.y, a1.y),
                           fmaxf(a0.z, a1.z), fmaxf(a0.w, a1.w));
    if (s == e) r = make_float4(0.f, 0.f, 0.f, 0.f);
    *(float4*)(out + (size_t)n * (2 * D) + D + c) = r;
}

// ---------------------------------------------------------------------------
// Fork-join: gemm runs on a second stream, concurrent with the CSR build.
// Stream/event creation happens once (host resources, not device memory);
// the enqueued work is identical on every call -> deterministic & capturable.
static cudaStream_t g_s2 = 0;
static cudaEvent_t  g_evFork = 0, g_evJoin = 0;

extern "C" void kernel_launch(void* const* d_in, const int* in_sizes, int n_in,
                              void* d_out, int out_size) {
    const float* x  = (const float*)d_in[0];
    const float* W  = (const float*)d_in[1];
    const void*  ei = d_in[2];
    float* out = (float*)d_out;

    if (!g_s2) {
        cudaStreamCreateWithFlags(&g_s2, cudaStreamNonBlocking);
        cudaEventCreateWithFlags(&g_evFork, cudaEventDisableTiming);
        cudaEventCreateWithFlags(&g_evJoin, cudaEventDisableTiming);
    }

    // Fork: gemm on s2 (independent of CSR build)
    cudaEventRecord(g_evFork, 0);
    cudaStreamWaitEvent(g_s2, g_evFork, 0);
    k_gemm<<<(NN / 4 + 7) / 8, 256, 0, g_s2>>>(x, W);
    cudaEventRecord(g_evJoin, g_s2);

    // CSR build chain on the main stream
    k_init <<<(NN + 255) / 256, 256>>>((const int*)ei);
    k_hist <<<NE / 256, 256>>>(ei);
    k_scan <<<1, 1024>>>();
    k_place<<<NE / 256, 256>>>(ei);

    // Join, then pool (needs g_norm + CSR)
    cudaStreamWaitEvent(0, g_evJoin, 0);
    k_pool <<<NN / 8, 256>>>(x, out);
}

// round 14
// speedup vs baseline: 1.9456x; 1.0965x over previous
#include <cuda_runtime.h>
#include <cuda_fp16.h>
#include <math.h>

#define NN 50000
#define D  128
#define NE 800000

// ---------------- device scratch (static globals: allowed) ----------------
__device__ __align__(16) __half g_normh[NN * D]; // x @ W1 in fp16 (12.8 MB)
__device__ __align__(16) int    g_deg[NN];
__device__ __align__(16) int    g_off[NN + 4];   // padded for int4 stores
__device__ __align__(16) int    g_cur[NN];
__device__ int    g_csr[NE];                     // rows bucketed by dest
__device__ int    g_is64;

// ---- f32x2 packed-FMA helpers (sm_103a FFMA2 path, PTX-only) --------------
__device__ __forceinline__ unsigned long long splat2(float x) {
    unsigned long long r;
    asm("mov.b64 %0, {%1, %1};" : "=l"(r) : "f"(x));
    return r;
}
__device__ __forceinline__ void ffma2(unsigned long long& acc,
                                      unsigned long long a,
                                      unsigned long long b) {
    asm("fma.rn.f32x2 %0, %1, %2, %0;" : "+l"(acc) : "l"(a), "l"(b));
}
__device__ __forceinline__ float2 unpack2(unsigned long long v) {
    float lo, hi;
    asm("mov.b64 {%0, %1}, %2;" : "=f"(lo), "=f"(hi) : "l"(v));
    return make_float2(lo, hi);
}

// ---------------- K0: zero degree counters + detect edge dtype ------------
__global__ void k_init(const int* __restrict__ ei32) {
    int i = blockIdx.x * blockDim.x + threadIdx.x;
    if (i < NN) g_deg[i] = 0;
    if (blockIdx.x == 0) {
        __shared__ int ok;
        if (threadIdx.x == 0) ok = 1;
        __syncthreads();
        int bad = 0;
        // int64 (LE): odd 32-bit words are high halves == 0 (values < 50000).
        // int32: those words are random indices -> nonzero with certainty.
        for (int t = threadIdx.x; t < 2048; t += blockDim.x)
            if (ei32[2 * t + 1] != 0) bad = 1;
        if (bad) ok = 0;
        __syncthreads();
        if (threadIdx.x == 0) g_is64 = ok;
    }
}

// ---------------- K1: GEMM  g_norm = x @ W1  (packed f32x2 FMA, fp16 out) --
__global__ void k_gemm(const float* __restrict__ x, const float* __restrict__ W) {
    int gw   = (blockIdx.x * blockDim.x + threadIdx.x) >> 5;
    int lane = threadIdx.x & 31;
    int r0   = gw * 4;
    if (r0 >= NN) return;

    const float* xp = x + (size_t)r0 * D;
    int c = lane * 4;

    unsigned long long acc[4][2];
#pragma unroll
    for (int r = 0; r < 4; r++) { acc[r][0] = 0ull; acc[r][1] = 0ull; }

#pragma unroll 2
    for (int k = 0; k < D; k += 4) {
        float4 xv0 = *(const float4*)(xp + k);
        float4 xv1 = *(const float4*)(xp + D + k);
        float4 xv2 = *(const float4*)(xp + 2 * D + k);
        float4 xv3 = *(const float4*)(xp + 3 * D + k);
        const float* px0 = (const float*)&xv0;
        const float* px1 = (const float*)&xv1;
        const float* px2 = (const float*)&xv2;
        const float* px3 = (const float*)&xv3;
#pragma unroll
        for (int kk = 0; kk < 4; kk++) {
            ulonglong2 w = *(const ulonglong2*)(W + (k + kk) * D + c);
            unsigned long long b0 = splat2(px0[kk]);
            unsigned long long b1 = splat2(px1[kk]);
            unsigned long long b2 = splat2(px2[kk]);
            unsigned long long b3 = splat2(px3[kk]);
            ffma2(acc[0][0], w.x, b0); ffma2(acc[0][1], w.y, b0);
            ffma2(acc[1][0], w.x, b1); ffma2(acc[1][1], w.y, b1);
            ffma2(acc[2][0], w.x, b2); ffma2(acc[2][1], w.y, b2);
            ffma2(acc[3][0], w.x, b3); ffma2(acc[3][1], w.y, b3);
        }
    }

    __half* oh = g_normh + (size_t)r0 * D + c;
#pragma unroll
    for (int r = 0; r < 4; r++) {
        float2 lo = unpack2(acc[r][0]);
        float2 hi = unpack2(acc[r][1]);
        union { __half2 h; unsigned u; } p0, p1;
        p0.h = __float22half2_rn(lo);
        p1.h = __float22half2_rn(hi);
        uint2 u = make_uint2(p0.u, p1.u);
        *(uint2*)(oh + (size_t)r * D) = u;
    }
}

// ---------------- K1b: copy x into out[:, :128] (independent branch) ------
__global__ void k_copyx(const float* __restrict__ x, float* __restrict__ out) {
    int i = blockIdx.x * blockDim.x + threadIdx.x;   // NN*32 threads
    int n = i >> 5, c = (i & 31) * 4;
    if (n >= NN) return;
    *(float4*)(out + (size_t)n * (2 * D) + c) =
        *(const float4*)(x + (size_t)n * D + c);
}

// ---------------- K2: histogram of destination degrees --------------------
__global__ void k_hist(const void* __restrict__ ei) {
    int e = blockIdx.x * blockDim.x + threadIdx.x;   // grid sized exactly NE
    int col;
    if (g_is64) col = (int)((const long long*)ei)[NE + e];
    else        col = ((const int*)ei)[NE + e];
    atomicAdd(&g_deg[col], 1);
}

// ---------------- K3: exclusive scan — batched ILP, reg-bounded ------------
__global__ void __launch_bounds__(1024) k_scan() {
    __shared__ int wtot[32];
    int tid = threadIdx.x, lane = tid & 31, wid = tid >> 5;
    const int NT4 = NN / 4;                        // 12500 int4 groups
    const int PERW = 391, ITER = 13, B = 5;
    int g0 = wid * PERW;
    int g1 = min(g0 + PERW, NT4);

    // Phase 1: warp totals
    int sum = 0;
    for (int g = g0 + lane; g < g1; g += 32) {
        int4 d = ((const int4*)g_deg)[g];
        sum += d.x + d.y + d.z + d.w;
    }
#pragma unroll
    for (int off = 16; off > 0; off >>= 1)
        sum += __shfl_xor_sync(0xffffffffu, sum, off);
    if (lane == 0) wtot[wid] = sum;
    __syncthreads();
    if (wid == 0) {
        int w = wtot[lane];
#pragma unroll
        for (int off = 1; off < 32; off <<= 1) {
            int t = __shfl_up_sync(0xffffffffu, w, off);
            if (lane >= off) w += t;
        }
        wtot[lane] = w;                            // inclusive
    }
    __syncthreads();

    // Phase 2: batched write-out
    int carry = wid ? wtot[wid - 1] : 0;
#pragma unroll
    for (int b = 0; b < ITER; b += B) {
        int4 d[B]; int s3v[B], inc[B];
#pragma unroll
        for (int j = 0; j < B; j++) {
            int i = b + j;
            int g = g0 + i * 32 + lane;
            d[j] = (i < ITER && g < g1) ? ((const int4*)g_deg)[g]
                                        : make_int4(0, 0, 0, 0);
        }
#pragma unroll
        for (int j = 0; j < B; j++) {
            s3v[j] = d[j].x + d[j].y + d[j].z + d[j].w;
            int v = s3v[j];
#pragma unroll
            for (int off = 1; off < 32; off <<= 1) {
                int t = __shfl_up_sync(0xffffffffu, v, off);
                if (lane >= off) v += t;
            }
            inc[j] = v;
        }
#pragma unroll
        for (int j = 0; j < B; j++) {
            int i = b + j;
            int g = g0 + i * 32 + lane;
            if (i < ITER && g < g1) {
                int excl = carry + inc[j] - s3v[j];
                int t0 = d[j].x, t1 = t0 + d[j].y, t2 = t1 + d[j].z;
                int4 o = make_int4(excl, excl + t0, excl + t1, excl + t2);
                ((int4*)g_off)[g] = o;
                ((int4*)g_cur)[g] = o;
            }
            carry += __shfl_sync(0xffffffffu, inc[j], 31);
        }
    }
    if (tid == 0) g_off[NN] = wtot[31];            // == NE (NN % 4 == 0)
}

// ---------------- K4: bucket placement (build CSR) -------------------------
__global__ void k_place(const void* __restrict__ ei) {
    int e = blockIdx.x * blockDim.x + threadIdx.x;   // grid sized exactly NE
    int row, col;
    if (g_is64) {
        row = (int)((const long long*)ei)[e];
        col = (int)((const long long*)ei)[NE + e];
    } else {
        row = ((const int*)ei)[e];
        col = ((const int*)ei)[NE + e];
    }
    int p = atomicAdd(&g_cur[col], 1);
    g_csr[p] = row;
}

// ---------------- K5: per-destination fp16 max-pool ------------------------
// One warp per destination. Lane l owns cols [4l,4l+4) = 2 half2. Gather
// traffic halved vs fp32; max is comparison-only so fp16 error = rounding
// of the stored value (<= 2^-11 relative). Output written fp32.
__global__ void k_pool(float* __restrict__ out) {
    int gw   = (blockIdx.x * blockDim.x + threadIdx.x) >> 5;
    int lane = threadIdx.x & 31;
    if (gw >= NN) return;
    int n = gw, c = lane * 4;

    int s = g_off[n], e = g_off[n + 1];
    const __half2 NIH = __half2half2(__ushort_as_half((unsigned short)0xFC00));
    __half2 a00 = NIH, a01 = NIH, a10 = NIH, a11 = NIH;

    int i = s;
    for (; i + 2 <= e; i += 2) {                   // 2-way MLP
        int r0 = g_csr[i], r1 = g_csr[i + 1];
        uint2 u0 = *(const uint2*)(g_normh + (size_t)r0 * D + c);
        uint2 u1 = *(const uint2*)(g_normh + (size_t)r1 * D + c);
        a00 = __hmax2(a00, *(__half2*)&u0.x);
        a01 = __hmax2(a01, *(__half2*)&u0.y);
        a10 = __hmax2(a10, *(__half2*)&u1.x);
        a11 = __hmax2(a11, *(__half2*)&u1.y);
    }
    if (i < e) {
        int r0 = g_csr[i];
        uint2 u0 = *(const uint2*)(g_normh + (size_t)r0 * D + c);
        a00 = __hmax2(a00, *(__half2*)&u0.x);
        a01 = __hmax2(a01, *(__half2*)&u0.y);
    }
    a00 = __hmax2(a00, a10);
    a01 = __hmax2(a01, a11);

    float2 f0 = __half22float2(a00);
    float2 f1 = __half22float2(a01);
    float4 r = make_float4(f0.x, f0.y, f1.x, f1.y);
    if (s == e) r = make_float4(0.f, 0.f, 0.f, 0.f);
    *(float4*)(out + (size_t)n * (2 * D) + D + c) = r;
}

// ---------------------------------------------------------------------------
// Fork-join: gemm + x-copy run on a second stream, concurrent with CSR build.
static cudaStream_t g_s2 = 0;
static cudaEvent_t  g_evFork = 0, g_evJoin = 0;

extern "C" void kernel_launch(void* const* d_in, const int* in_sizes, int n_in,
                              void* d_out, int out_size) {
    const float* x  = (const float*)d_in[0];
    const float* W  = (const float*)d_in[1];
    const void*  ei = d_in[2];
    float* out = (float*)d_out;

    if (!g_s2) {
        cudaStreamCreateWithFlags(&g_s2, cudaStreamNonBlocking);
        cudaEventCreateWithFlags(&g_evFork, cudaEventDisableTiming);
        cudaEventCreateWithFlags(&g_evJoin, cudaEventDisableTiming);
    }

    // Fork: gemm + copyx on s2 (independent of CSR build)
    cudaEventRecord(g_evFork, 0);
    cudaStreamWaitEvent(g_s2, g_evFork, 0);
    k_gemm <<<(NN / 4 + 7) / 8, 256, 0, g_s2>>>(x, W);
    k_copyx<<<(NN * 32 + 255) / 256, 256, 0, g_s2>>>(x, out);
    cudaEventRecord(g_evJoin, g_s2);

    // CSR build chain on the main stream
    k_init <<<(NN + 255) / 256, 256>>>((const int*)ei);
    k_hist <<<NE / 256, 256>>>(ei);
    k_scan <<<1, 1024>>>();
    k_place<<<NE / 256, 256>>>(ei);

    // Join, then pool (needs g_normh + CSR; copyx must also precede completion)
    cudaStreamWaitEvent(0, g_evJoin, 0);
    k_pool <<<NN / 8, 256>>>(out);
}